// round 7
// baseline (speedup 1.0000x reference)
#include <cuda_runtime.h>

#define BATCH 16384
#define CTX   10
#define MAXC  24
#define EMBED 128
#define WPB   8
#define THREADS (WPB * 32)
#define GRID  ((BATCH + WPB - 1) / WPB)   // 2048
#define PITCH 36   // 36 words/row: STS banks (4l+i)%32 distinct; 144B rows -> 16B aligned, LDS.128 conflict-free
#define SLOT_STRIDE 64   // 64 floats = 256B between accumulator slots -> distinct L2 slices (bit7 transparent)

// Per-step-loss accumulators, 256B apart. Zero-initialized at module load;
// publish_kernel resets them after reading, so every launch (and every graph
// replay) sees a clean state. No allocation anywhere.
__device__ float g_part[MAXC * SLOT_STRIDE];

// Predicated vector gather: @p LDG.E.128, no branch; e stays 0 when pred==0.
__device__ __forceinline__ float4 pred_ldg128(const float4* addr, int pred) {
    float4 e = make_float4(0.f, 0.f, 0.f, 0.f);
    asm("{\n\t"
        ".reg .pred p;\n\t"
        "setp.ne.s32 p, %4, 0;\n\t"
        "@p ld.global.nc.v4.f32 {%0,%1,%2,%3}, [%5];\n\t"
        "}"
        : "+f"(e.x), "+f"(e.y), "+f"(e.z), "+f"(e.w)
        : "r"(pred), "l"(addr));
    return e;
}

__global__ __launch_bounds__(THREADS, 6)   // measured optimum: MLP 8/chain @ 6 blocks/SM
void cbow_hs_kernel(const int* __restrict__ context_words,
                    const int* __restrict__ paths,
                    const int* __restrict__ codes,
                    const int* __restrict__ mask,     // int32 0/1
                    const float* __restrict__ W_in,
                    const float* __restrict__ W_internal)
{
    const int warp_id = threadIdx.x >> 5;
    const int lane    = threadIdx.x & 31;
    const int row     = blockIdx.x * WPB + warp_id;

    __shared__ float wsum[WPB][MAXC * PITCH];   // 27.6 KB, warp-private slices

    if (row >= BATCH) return;

    // ---- Phase 1: context vector (mean of 10 gathered 512B rows).
    const int* cw = context_words + row * CTX;
    float4 v = make_float4(0.f, 0.f, 0.f, 0.f);
    #pragma unroll
    for (int i = 0; i < CTX; i++) {
        const int w = cw[i];
        const float4 e = __ldg(reinterpret_cast<const float4*>(
                                   W_in + (long)w * EMBED) + lane);
        v.x += e.x; v.y += e.y; v.z += e.z; v.w += e.w;
    }
    const float inv_ctx = 1.0f / (float)CTX;
    v.x *= inv_ctx; v.y *= inv_ctx; v.z *= inv_ctx; v.w *= inv_ctx;

    // ---- Phase 2: 24 predicated gathers in 3 batches of 8 (MLP 8 per
    // dependency chain — measured optimum); partial dots stored to smem
    // right after each batch.
    float* ws = wsum[warp_id];
    const int4* p4 = reinterpret_cast<const int4*>(paths + row * MAXC);
    const int4* m4 = reinterpret_cast<const int4*>(mask  + row * MAXC);

    #pragma unroll
    for (int h = 0; h < 3; h++) {
        const int4 P0 = __ldg(p4 + h * 2), P1 = __ldg(p4 + h * 2 + 1);
        const int4 M0 = __ldg(m4 + h * 2), M1 = __ldg(m4 + h * 2 + 1);
        const int nodes[8] = {P0.x, P0.y, P0.z, P0.w, P1.x, P1.y, P1.z, P1.w};
        const int mks[8]   = {M0.x, M0.y, M0.z, M0.w, M1.x, M1.y, M1.z, M1.w};

        float4 E[8];
        #pragma unroll
        for (int k = 0; k < 8; k++)
            E[k] = pred_ldg128(reinterpret_cast<const float4*>(
                                   W_internal + (long)nodes[k] * EMBED) + lane,
                               mks[k]);
        #pragma unroll
        for (int k = 0; k < 8; k++) {
            const float pt = fmaf(v.x, E[k].x,
                             fmaf(v.y, E[k].y,
                             fmaf(v.z, E[k].z, v.w * E[k].w)));
            ws[(h * 8 + k) * PITCH + lane] = pt;   // conflict-free STS
        }
    }
    __syncwarp();

    // ---- Phase 3: lane j (<24) sums step j's 32 partials via 8x LDS.128,
    // applies softplus, and fires ONE red.global.add into its padded slot.
    // No shuffles, no smem block reduce, no __syncthreads: warps are fully
    // decoupled and retire independently.
    if (lane < MAXC) {
        const float4* rp = reinterpret_cast<const float4*>(ws + lane * PITCH);
        float4 a0 = rp[0], a1 = rp[1], a2 = rp[2], a3 = rp[3];
        const float4 b0 = rp[4], b1 = rp[5], b2 = rp[6], b3 = rp[7];
        a0.x += b0.x; a0.y += b0.y; a0.z += b0.z; a0.w += b0.w;
        a1.x += b1.x; a1.y += b1.y; a1.z += b1.z; a1.w += b1.w;
        a2.x += b2.x; a2.y += b2.y; a2.z += b2.z; a2.w += b2.w;
        a3.x += b3.x; a3.y += b3.y; a3.z += b3.z; a3.w += b3.w;
        float s = ((a0.x + a0.y) + (a0.z + a0.w))
                + ((a1.x + a1.y) + (a1.z + a1.w))
                + ((a2.x + a2.y) + (a2.z + a2.w))
                + ((a3.x + a3.y) + (a3.z + a3.w));

        const int cj = codes[row * MAXC + lane];
        const int mj = mask [row * MAXC + lane];
        const float sign = (float)(2 * cj - 1);
        const float x = -sign * s;
        // softplus(x) = max(x,0) + log(1 + exp(-|x|)), MUFU fast path
        const float sp = fmaxf(x, 0.0f) + __logf(1.0f + __expf(-fabsf(x)));
        if (mj)
            atomicAdd(&g_part[lane * SLOT_STRIDE], sp);   // REDG, result unused
    }
}

// Reads the 24 slots, resets them for the next replay, publishes the mean.
// Kernel boundary (implicit sync + per-launch L1 flush) provides all the
// ordering the R6 in-kernel __threadfence was paying CCTL.IVALL for.
__global__ void publish_kernel(float* __restrict__ out) {
    const int lane = threadIdx.x;
    float v = 0.0f;
    if (lane < MAXC) {
        v = g_part[lane * SLOT_STRIDE];
        g_part[lane * SLOT_STRIDE] = 0.0f;
    }
    v += __shfl_xor_sync(0xffffffffu, v, 16);
    v += __shfl_xor_sync(0xffffffffu, v, 8);
    v += __shfl_xor_sync(0xffffffffu, v, 4);
    v += __shfl_xor_sync(0xffffffffu, v, 2);
    v += __shfl_xor_sync(0xffffffffu, v, 1);
    if (lane == 0) out[0] = v * (1.0f / (float)BATCH);
}

extern "C" void kernel_launch(void* const* d_in, const int* in_sizes, int n_in,
                              void* d_out, int out_size)
{
    const int*   context_words = (const int*)d_in[0];
    const int*   paths         = (const int*)d_in[1];
    const int*   codes         = (const int*)d_in[2];
    const int*   mask          = (const int*)d_in[3];
    const float* W_in          = (const float*)d_in[4];
    const float* W_internal    = (const float*)d_in[5];
    float*       out           = (float*)d_out;

    cbow_hs_kernel<<<GRID, THREADS>>>(context_words, paths, codes, mask,
                                      W_in, W_internal);
    publish_kernel<<<1, 32>>>(out);
}

// round 8
// speedup vs baseline: 1.3384x; 1.3384x over previous
#include <cuda_runtime.h>

#define BATCH 16384
#define CTX   10
#define MAXC  24
#define EMBED 128
#define WPB   8
#define THREADS (WPB * 32)
#define GRID  ((BATCH + WPB - 1) / WPB)   // 2048
#define PITCH 36   // 36 words/row: STS banks (4l+i)%32 distinct; 144B rows -> 16B aligned, LDS.128 conflict-free

__global__ void zero_out_kernel(float* out) {
    if (threadIdx.x == 0) out[0] = 0.0f;
}

// Predicated vector gather: @p LDG.E.128, no branch; e stays 0 when pred==0.
__device__ __forceinline__ float4 pred_ldg128(const float4* addr, int pred) {
    float4 e = make_float4(0.f, 0.f, 0.f, 0.f);
    asm("{\n\t"
        ".reg .pred p;\n\t"
        "setp.ne.s32 p, %4, 0;\n\t"
        "@p ld.global.nc.v4.f32 {%0,%1,%2,%3}, [%5];\n\t"
        "}"
        : "+f"(e.x), "+f"(e.y), "+f"(e.z), "+f"(e.w)
        : "r"(pred), "l"(addr));
    return e;
}

// Issue one batch of 8 predicated node gathers.
__device__ __forceinline__ void issue_batch(float4 E[8],
                                            const int4* p4, const int4* m4,
                                            int h, const float* W_internal,
                                            int lane) {
    const int4 P0 = __ldg(p4 + h * 2), P1 = __ldg(p4 + h * 2 + 1);
    const int4 M0 = __ldg(m4 + h * 2), M1 = __ldg(m4 + h * 2 + 1);
    const int nodes[8] = {P0.x, P0.y, P0.z, P0.w, P1.x, P1.y, P1.z, P1.w};
    const int mks[8]   = {M0.x, M0.y, M0.z, M0.w, M1.x, M1.y, M1.z, M1.w};
    #pragma unroll
    for (int k = 0; k < 8; k++)
        E[k] = pred_ldg128(reinterpret_cast<const float4*>(
                               W_internal + (long)nodes[k] * EMBED) + lane,
                           mks[k]);
}

// Consume one batch: dot with v, store partials to the warp's smem transpose slice.
__device__ __forceinline__ void consume_batch(const float4 E[8], float4 v,
                                              float* ws, int h, int lane) {
    #pragma unroll
    for (int k = 0; k < 8; k++) {
        const float pt = fmaf(v.x, E[k].x,
                         fmaf(v.y, E[k].y,
                         fmaf(v.z, E[k].z, v.w * E[k].w)));
        ws[(h * 8 + k) * PITCH + lane] = pt;   // conflict-free STS
    }
}

__global__ __launch_bounds__(THREADS, 5)   // 51-reg cap: room for the prefetched batch
void cbow_hs_kernel(const int* __restrict__ context_words,
                    const int* __restrict__ paths,
                    const int* __restrict__ codes,
                    const int* __restrict__ mask,     // int32 0/1
                    const float* __restrict__ W_in,
                    const float* __restrict__ W_internal,
                    float* __restrict__ out)
{
    const int warp_id = threadIdx.x >> 5;
    const int lane    = threadIdx.x & 31;
    const int row     = blockIdx.x * WPB + warp_id;

    __shared__ float wsum[WPB][MAXC * PITCH];   // 27.6 KB
    __shared__ float warp_loss[WPB];

    float contrib = 0.0f;

    if (row < BATCH) {
        float* ws = wsum[warp_id];
        const int4* p4 = reinterpret_cast<const int4*>(paths + row * MAXC);
        const int4* m4 = reinterpret_cast<const int4*>(mask  + row * MAXC);

        // ---- Software pipeline: node batch 0 issued FIRST. Its 600-cycle
        // round trip hides entirely behind the context-gather round trip
        // (the gathers depend only on indices, not on v).
        float4 E[8];
        issue_batch(E, p4, m4, 0, W_internal, lane);

        // ---- Phase 1: context vector (mean of 10 gathered 512B rows),
        // overlapped with batch-0 in flight.
        const int* cw = context_words + row * CTX;
        float4 v = make_float4(0.f, 0.f, 0.f, 0.f);
        #pragma unroll
        for (int i = 0; i < CTX; i++) {
            const int w = cw[i];
            const float4 e = __ldg(reinterpret_cast<const float4*>(
                                       W_in + (long)w * EMBED) + lane);
            v.x += e.x; v.y += e.y; v.z += e.z; v.w += e.w;
        }
        const float inv_ctx = 1.0f / (float)CTX;
        v.x *= inv_ctx; v.y *= inv_ctx; v.z *= inv_ctx; v.w *= inv_ctx;

        // ---- Phase 2: consume batch 0 (already arrived), then batches 1,2.
        consume_batch(E, v, ws, 0, lane);
        issue_batch(E, p4, m4, 1, W_internal, lane);
        consume_batch(E, v, ws, 1, lane);
        issue_batch(E, p4, m4, 2, W_internal, lane);
        consume_batch(E, v, ws, 2, lane);
        __syncwarp();

        // ---- Phase 3: lane j (<24) sums step j's 32 partials via 8x LDS.128.
        if (lane < MAXC) {
            const float4* rp = reinterpret_cast<const float4*>(ws + lane * PITCH);
            float4 a0 = rp[0], a1 = rp[1], a2 = rp[2], a3 = rp[3];
            const float4 b0 = rp[4], b1 = rp[5], b2 = rp[6], b3 = rp[7];
            a0.x += b0.x; a0.y += b0.y; a0.z += b0.z; a0.w += b0.w;
            a1.x += b1.x; a1.y += b1.y; a1.z += b1.z; a1.w += b1.w;
            a2.x += b2.x; a2.y += b2.y; a2.z += b2.z; a2.w += b2.w;
            a3.x += b3.x; a3.y += b3.y; a3.z += b3.z; a3.w += b3.w;
            float s = ((a0.x + a0.y) + (a0.z + a0.w))
                    + ((a1.x + a1.y) + (a1.z + a1.w))
                    + ((a2.x + a2.y) + (a2.z + a2.w))
                    + ((a3.x + a3.y) + (a3.z + a3.w));

            const int cj = codes[row * MAXC + lane];
            const int mj = mask [row * MAXC + lane];
            const float sign = (float)(2 * cj - 1);
            const float x = -sign * s;
            // softplus(x) = max(x,0) + log(1 + exp(-|x|)), MUFU fast path
            const float sp = fmaxf(x, 0.0f) + __logf(1.0f + __expf(-fabsf(x)));
            contrib = mj ? sp : 0.0f;
        }
    }

    // ---- R4 reduction (measured optimum): warp shuffles -> smem -> one
    // atomicAdd per block.
    contrib += __shfl_xor_sync(0xffffffffu, contrib, 16);
    contrib += __shfl_xor_sync(0xffffffffu, contrib, 8);
    contrib += __shfl_xor_sync(0xffffffffu, contrib, 4);
    contrib += __shfl_xor_sync(0xffffffffu, contrib, 2);
    contrib += __shfl_xor_sync(0xffffffffu, contrib, 1);

    if (lane == 0) warp_loss[warp_id] = contrib;
    __syncthreads();

    if (warp_id == 0) {
        float s = (lane < WPB) ? warp_loss[lane] : 0.0f;
        s += __shfl_xor_sync(0xffffffffu, s, 4);
        s += __shfl_xor_sync(0xffffffffu, s, 2);
        s += __shfl_xor_sync(0xffffffffu, s, 1);
        if (lane == 0) atomicAdd(out, s * (1.0f / (float)BATCH));
    }
}

extern "C" void kernel_launch(void* const* d_in, const int* in_sizes, int n_in,
                              void* d_out, int out_size)
{
    const int*   context_words = (const int*)d_in[0];
    const int*   paths         = (const int*)d_in[1];
    const int*   codes         = (const int*)d_in[2];
    const int*   mask          = (const int*)d_in[3];
    const float* W_in          = (const float*)d_in[4];
    const float* W_internal    = (const float*)d_in[5];
    float*       out           = (float*)d_out;

    zero_out_kernel<<<1, 32>>>(out);

    cbow_hs_kernel<<<GRID, THREADS>>>(context_words, paths, codes, mask,
                                      W_in, W_internal, out);
}